// round 4
// baseline (speedup 1.0000x reference)
#include <cuda_runtime.h>

// Problem constants (shapes fixed by dataset; code stays correct for any
// batch_list via the offsets kernel + generic path).
#define D_DIM   300          // embedding dim
#define DC      60           // columns per chunk (multiple of 4, divides 300)
#define DC4     (DC / 4)     // 15 float4 per row-chunk
#define NCHUNK  (D_DIM / DC) // 5
#define TR      256          // row tile (== nodes per graph in this dataset)
#define RB      16           // row-blocks
#define NT      (RB * DC4)   // 240 threads per CTA
#define KIT     (TR / RB)    // 16 rows per thread in fast path
#define MAXB    8192
#define EPSV    1e-12f

// Scratch (no cudaMalloc allowed): per-graph row offsets + actual graph count.
__device__ int g_off[MAXB + 1];
__device__ int g_B;

// ---------------------------------------------------------------------------
// Offsets kernel: detects int32 vs int64 batch_list layout. Fast path: if all
// counts are equal (dataset case), writes offsets arithmetically with no scan.
// Fallback: block-wide inclusive scan.
// ---------------------------------------------------------------------------
__global__ void offsets_kernel(const int* __restrict__ p32, int nb, int ntot) {
    __shared__ int sh[1024];
    __shared__ int s_stride, s_carry, s_uni, s_val;
    const int tid = threadIdx.x;

    if (tid == 0) {
        int stride = 1;
        if (nb > 1) {
            int v0 = p32[0], v1 = p32[1];
            if (v1 == 0 && v0 != 0) stride = 2;   // int64 little-endian
        }
        s_stride = stride;
        s_carry = 0;
        s_uni = 1;
        s_val = p32[0];
        g_off[0] = 0;
    }
    __syncthreads();

    const int st = s_stride;
    int B = nb;
    if (B > MAXB) B = MAXB;
    const int B1 = (st == 2) ? (B >> 1) : B;
    const int v0 = s_val;

    int uni = 1;
    for (int i = tid; i < B1; i += 1024)
        if (p32[(size_t)i * st] != v0) uni = 0;
    if (!uni) atomicAnd(&s_uni, 0);
    __syncthreads();

    if (s_uni && (long long)B1 * v0 == ntot) {
        for (int i = tid; i < B1; i += 1024)
            g_off[i + 1] = (i + 1) * v0;
        if (tid == 0) g_B = B1;
        return;
    }

    for (int base = 0; base < B1; base += 1024) {
        int i = base + tid;
        int v = (i < B1) ? p32[(size_t)i * st] : 0;
        sh[tid] = v;
        __syncthreads();
        #pragma unroll
        for (int o = 1; o < 1024; o <<= 1) {
            int t = (tid >= o) ? sh[tid - o] : 0;
            __syncthreads();
            sh[tid] += t;
            __syncthreads();
        }
        if (i < B1) g_off[i + 1] = s_carry + sh[tid];
        __syncthreads();
        if (tid == 0) s_carry += sh[1023];
        __syncthreads();
    }

    int Bfinal = B1;
    if (st == 2 && B1 > 0 && g_off[B1] != ntot && B > B1) {
        for (int base = B1; base < B; base += 1024) {
            int i = base + tid;
            int v = (i < B) ? p32[(size_t)i * st] : 0;
            sh[tid] = v;
            __syncthreads();
            #pragma unroll
            for (int o = 1; o < 1024; o <<= 1) {
                int t = (tid >= o) ? sh[tid - o] : 0;
                __syncthreads();
                sh[tid] += t;
                __syncthreads();
            }
            if (i < B) g_off[i + 1] = s_carry + sh[tid];
            __syncthreads();
            if (tid == 0) s_carry += sh[1023];
            __syncthreads();
        }
        Bfinal = B;
    }
    if (tid == 0) g_B = Bfinal;
}

// ---------------------------------------------------------------------------
// Helpers
// ---------------------------------------------------------------------------
__device__ __forceinline__ float4 min4(float4 a, float4 b) {
    return make_float4(fminf(a.x, b.x), fminf(a.y, b.y),
                       fminf(a.z, b.z), fminf(a.w, b.w));
}
__device__ __forceinline__ float4 max4(float4 a, float4 b) {
    return make_float4(fmaxf(a.x, b.x), fmaxf(a.y, b.y),
                       fmaxf(a.z, b.z), fmaxf(a.w, b.w));
}

// ---------------------------------------------------------------------------
// Main kernel: one CTA per (graph, 60-column chunk). Two passes:
//   pass1: stream rows from gmem (stays L2-resident), min/max in registers.
//   reduce: 2 barriers — partials to smem, 15 threads fold + publish mid/inv.
//   pass2: re-read rows (__ldcs: L2 hit, evict-first), normalize, __stcs out.
// Low register count -> 7 CTAs/SM; phases across CTAs decorrelate, keeping
// DRAM busy. DRAM traffic: one read + one write of the tensor.
// ---------------------------------------------------------------------------
__global__ void __launch_bounds__(NT, 7)
cube_norm_kernel(const float* __restrict__ x, float* __restrict__ y) {
    __shared__ float4 s_mn[RB][DC4];   // 3840 B
    __shared__ float4 s_mx[RB][DC4];   // 3840 B
    __shared__ float4 s_mid[DC4];      // 240 B
    __shared__ float4 s_inv[DC4];      // 240 B

    const int g = blockIdx.y;
    if (g >= g_B) return;
    const int c0 = blockIdx.x * DC;
    const int r0 = g_off[g];
    const int nr = g_off[g + 1] - r0;
    if (nr <= 0) return;

    const int tid = threadIdx.x;
    const int j   = tid % DC4;         // column quad 0..14
    const int rb  = tid / DC4;         // row block 0..15

    const float* xg = x + (size_t)r0 * D_DIM + c0 + 4 * j;
    float*       yg = y + (size_t)r0 * D_DIM + c0 + 4 * j;
    const float* p  = xg + (size_t)rb * D_DIM;
    float*       q  = yg + (size_t)rb * D_DIM;

    if (nr == TR) {
        // ---- pass 1: stream + reduce in flight (default .ca -> L2 keeps it)
        float4 mn, mx;
        {
            float4 a = *(const float4*)p;
            mn = a; mx = a;
        }
        #pragma unroll 5
        for (int k = 1; k < KIT; k++) {
            float4 a = *(const float4*)(p + (size_t)k * RB * D_DIM);
            mn = min4(mn, a);
            mx = max4(mx, a);
        }
        s_mn[rb][j] = mn;
        s_mx[rb][j] = mx;
        __syncthreads();

        // ---- fold partials: 15 threads, then broadcast ----
        if (tid < DC4) {
            float4 fmn = s_mn[0][tid];
            float4 fmx = s_mx[0][tid];
            #pragma unroll
            for (int r = 1; r < RB; r++) {
                fmn = min4(fmn, s_mn[r][tid]);
                fmx = max4(fmx, s_mx[r][tid]);
            }
            float4 mid = make_float4((fmx.x + fmn.x) * 0.5f,
                                     (fmx.y + fmn.y) * 0.5f,
                                     (fmx.z + fmn.z) * 0.5f,
                                     (fmx.w + fmn.w) * 0.5f);
            float4 inv = make_float4(
                1.0f / fmaxf((fmx.x - fmn.x) * 0.5f, EPSV),
                1.0f / fmaxf((fmx.y - fmn.y) * 0.5f, EPSV),
                1.0f / fmaxf((fmx.z - fmn.z) * 0.5f, EPSV),
                1.0f / fmaxf((fmx.w - fmn.w) * 0.5f, EPSV));
            s_mid[tid] = mid;
            s_inv[tid] = inv;
        }
        __syncthreads();

        const float4 mid = s_mid[j];
        const float4 inv = s_inv[j];

        // ---- pass 2: re-read (L2 hit, evict-first), normalize, stream out
        #pragma unroll 4
        for (int k = 0; k < KIT; k++) {
            float4 a = __ldcs((const float4*)(p + (size_t)k * RB * D_DIM));
            float4 o;
            o.x = (a.x - mid.x) * inv.x;
            o.y = (a.y - mid.y) * inv.y;
            o.z = (a.z - mid.z) * inv.z;
            o.w = (a.w - mid.w) * inv.w;
            __stcs((float4*)(q + (size_t)k * RB * D_DIM), o);
        }
    } else {
        // ---------------- generic two-sweep path (not hit by dataset) ------
        float4 mn = make_float4( 3.402823466e38f,  3.402823466e38f,
                                 3.402823466e38f,  3.402823466e38f);
        float4 mx = make_float4(-3.402823466e38f, -3.402823466e38f,
                                -3.402823466e38f, -3.402823466e38f);
        for (int r = rb; r < nr; r += RB) {
            float4 a = *(const float4*)(xg + (size_t)r * D_DIM);
            mn = min4(mn, a);
            mx = max4(mx, a);
        }
        s_mn[rb][j] = mn;
        s_mx[rb][j] = mx;
        __syncthreads();
        if (tid < DC4) {
            float4 fmn = s_mn[0][tid];
            float4 fmx = s_mx[0][tid];
            #pragma unroll
            for (int r = 1; r < RB; r++) {
                fmn = min4(fmn, s_mn[r][tid]);
                fmx = max4(fmx, s_mx[r][tid]);
            }
            float4 mid = make_float4((fmx.x + fmn.x) * 0.5f,
                                     (fmx.y + fmn.y) * 0.5f,
                                     (fmx.z + fmn.z) * 0.5f,
                                     (fmx.w + fmn.w) * 0.5f);
            float4 inv = make_float4(
                1.0f / fmaxf((fmx.x - fmn.x) * 0.5f, EPSV),
                1.0f / fmaxf((fmx.y - fmn.y) * 0.5f, EPSV),
                1.0f / fmaxf((fmx.z - fmn.z) * 0.5f, EPSV),
                1.0f / fmaxf((fmx.w - fmn.w) * 0.5f, EPSV));
            s_mid[tid] = mid;
            s_inv[tid] = inv;
        }
        __syncthreads();
        const float4 mid = s_mid[j];
        const float4 inv = s_inv[j];
        for (int r = rb; r < nr; r += RB) {
            float4 a = *(const float4*)(xg + (size_t)r * D_DIM);
            float4 o;
            o.x = (a.x - mid.x) * inv.x;
            o.y = (a.y - mid.y) * inv.y;
            o.z = (a.z - mid.z) * inv.z;
            o.w = (a.w - mid.w) * inv.w;
            *(float4*)(yg + (size_t)r * D_DIM) = o;
        }
    }
}

// ---------------------------------------------------------------------------
extern "C" void kernel_launch(void* const* d_in, const int* in_sizes, int n_in,
                              void* d_out, int out_size) {
    const float* x  = (const float*)d_in[0];
    const int*   bl = (const int*)d_in[1];
    float*       y  = (float*)d_out;

    const int nb   = in_sizes[1];
    const int ntot = in_sizes[0] / D_DIM;

    offsets_kernel<<<1, 1024>>>(bl, nb, ntot);

    int gy = nb < MAXB ? nb : MAXB;
    if (gy < 1) gy = 1;
    dim3 grid(NCHUNK, gy);
    cube_norm_kernel<<<grid, NT>>>(x, y);
}